// round 4
// baseline (speedup 1.0000x reference)
#include <cuda_runtime.h>
#include <mma.h>
#include <cstdint>
#include <cstddef>

using namespace nvcuda;

// ---------------------------------------------------------------------------
// Problem constants
// ---------------------------------------------------------------------------
static constexpr int D_MODEL = 1024;
static constexpr int N_HEAD  = 16;
static constexpr int N_KVH   = 4;
static constexpr int D_K     = 64;
static constexpr int Bb      = 2;
static constexpr int Ss      = 2048;
static constexpr int MTOT    = Bb * Ss;          // 4096
static constexpr int KV_D    = N_KVH * D_K;      // 256

// ---------------------------------------------------------------------------
// Scratch (no cudaMalloc allowed)
// ---------------------------------------------------------------------------
__device__ float g_Q[(size_t)MTOT * D_MODEL];
__device__ float g_K[(size_t)MTOT * KV_D];
__device__ float g_V[(size_t)MTOT * KV_D];
__device__ float g_O[(size_t)MTOT * D_MODEL];

__device__ __forceinline__ float ex2f(float x) {
    float y;
    asm("ex2.approx.ftz.f32 %0, %1;" : "=f"(y) : "f"(x));
    return y;
}
__device__ __forceinline__ float to_tf32(float x) {
    uint32_t y;
    asm("cvt.rna.tf32.f32 %0, %1;" : "=r"(y) : "f"(x));
    return __uint_as_float(y);
}

// mma.sync m16n8k8 tf32: D += A*B, A row-major 16x8, B col-major 8x8
__device__ __forceinline__ void mma_tf32(float c[4],
                                         uint32_t a0, uint32_t a1, uint32_t a2, uint32_t a3,
                                         uint32_t b0, uint32_t b1) {
    asm volatile(
        "mma.sync.aligned.m16n8k8.row.col.f32.tf32.tf32.f32 "
        "{%0,%1,%2,%3}, {%4,%5,%6,%7}, {%8,%9}, {%0,%1,%2,%3};\n"
        : "+f"(c[0]), "+f"(c[1]), "+f"(c[2]), "+f"(c[3])
        : "r"(a0), "r"(a1), "r"(a2), "r"(a3), "r"(b0), "r"(b1));
}

// ldmatrix x4: four 8x16B tiles; lanes 0-7/8-15/16-23/24-31 address tiles 0..3
__device__ __forceinline__ void ldsm_x4(uint32_t r[4], uint32_t addr) {
    asm volatile(
        "ldmatrix.sync.aligned.m8n8.x4.shared.b16 {%0,%1,%2,%3}, [%4];\n"
        : "=r"(r[0]), "=r"(r[1]), "=r"(r[2]), "=r"(r[3]) : "r"(addr));
}

// ---------------------------------------------------------------------------
// GEMM v2: C[M,N] = A[M,K] @ B[K,N]; block 128x128, K-step 32, 256 threads.
// 8 warps (2m x 4n), warp tile 64x32 = 4x2 m16n16k8 wmma frags.
// Register-staged gmem prefetch overlaps MMA phase.
// ---------------------------------------------------------------------------
static constexpr int GBM = 128, GBN = 128, GBK = 32;
static constexpr int LDA_S = GBK + 4;   // 36
static constexpr int LDB_S = GBN + 4;   // 132

__global__ __launch_bounds__(256) void gemm_tf32_kernel(
    const float* __restrict__ A, const float* __restrict__ Bm,
    float* __restrict__ C, int M, int N, int K)
{
    __shared__ __align__(16) float sA[GBM * LDA_S];
    __shared__ __align__(16) float sB[GBK * LDB_S];

    const int tid = threadIdx.x;
    const int wid = tid >> 5;
    const int wm  = wid >> 2;          // 0..1
    const int wn  = wid & 3;           // 0..3
    const int bm  = blockIdx.y * GBM;
    const int bn  = blockIdx.x * GBN;

    wmma::fragment<wmma::accumulator, 16, 16, 8, float> acc[4][2];
    #pragma unroll
    for (int i = 0; i < 4; i++)
        #pragma unroll
        for (int j = 0; j < 2; j++) wmma::fill_fragment(acc[i][j], 0.0f);

    // per-thread gmem staging: A 4 x float4, B 4 x float4
    float4 ra[4], rb[4];
    #pragma unroll
    for (int q = 0; q < 4; q++) {
        const int ia = tid + q * 256;           // A f4 index: row = ia>>3, c4=(ia&7)*4
        ra[q] = *(const float4*)&A[(size_t)(bm + (ia >> 3)) * K + (ia & 7) * 4];
        const int ib = tid + q * 256;           // B f4 index: row = ib>>5, c4=(ib&31)*4
        rb[q] = *(const float4*)&Bm[(size_t)(ib >> 5) * N + bn + (ib & 31) * 4];
    }

    for (int k0 = 0; k0 < K; k0 += GBK) {
        // commit staged regs to smem (tf32 rounding)
        #pragma unroll
        for (int q = 0; q < 4; q++) {
            const int ia = tid + q * 256;
            float* pa = &sA[(ia >> 3) * LDA_S + (ia & 7) * 4];
            pa[0] = to_tf32(ra[q].x); pa[1] = to_tf32(ra[q].y);
            pa[2] = to_tf32(ra[q].z); pa[3] = to_tf32(ra[q].w);
            const int ib = tid + q * 256;
            float* pb = &sB[(ib >> 5) * LDB_S + (ib & 31) * 4];
            pb[0] = to_tf32(rb[q].x); pb[1] = to_tf32(rb[q].y);
            pb[2] = to_tf32(rb[q].z); pb[3] = to_tf32(rb[q].w);
        }
        __syncthreads();

        // prefetch next K-chunk (overlaps MMA below)
        if (k0 + GBK < K) {
            #pragma unroll
            for (int q = 0; q < 4; q++) {
                const int ia = tid + q * 256;
                ra[q] = *(const float4*)&A[(size_t)(bm + (ia >> 3)) * K + k0 + GBK + (ia & 7) * 4];
                const int ib = tid + q * 256;
                rb[q] = *(const float4*)&Bm[(size_t)(k0 + GBK + (ib >> 5)) * N + bn + (ib & 31) * 4];
            }
        }

        #pragma unroll
        for (int kk = 0; kk < 4; kk++) {
            wmma::fragment<wmma::matrix_a, 16, 16, 8, wmma::precision::tf32, wmma::row_major> af[4];
            wmma::fragment<wmma::matrix_b, 16, 16, 8, wmma::precision::tf32, wmma::row_major> bf[2];
            #pragma unroll
            for (int i = 0; i < 4; i++)
                wmma::load_matrix_sync(af[i], &sA[(wm * 64 + i * 16) * LDA_S + kk * 8], LDA_S);
            #pragma unroll
            for (int j = 0; j < 2; j++)
                wmma::load_matrix_sync(bf[j], &sB[(kk * 8) * LDB_S + wn * 32 + j * 16], LDB_S);
            #pragma unroll
            for (int i = 0; i < 4; i++)
                #pragma unroll
                for (int j = 0; j < 2; j++)
                    wmma::mma_sync(acc[i][j], af[i], bf[j], acc[i][j]);
        }
        __syncthreads();
    }

    #pragma unroll
    for (int i = 0; i < 4; i++)
        #pragma unroll
        for (int j = 0; j < 2; j++)
            wmma::store_matrix_sync(
                &C[(size_t)(bm + wm * 64 + i * 16) * N + bn + wn * 32 + j * 16],
                acc[i][j], N, wmma::mem_row_major);
}

// ---------------------------------------------------------------------------
// Flash attention (GQA) with ldmatrix fragment loads.
// CTA = 128 q-rows x (b,h); 8 warps, warp owns 16 rows. d_k=64, KV tile 64.
// sQ/sK/sP row-major (LDS=68). V stored TRANSPOSED (sVt[d][kv], 64-f rows)
// with xor swizzle phys_chunk = chunk ^ (d&7) -> conflict-free LDSM.
// ---------------------------------------------------------------------------
static constexpr int QT  = 128;
static constexpr int KT  = 64;
static constexpr int LDS = 68;

static constexpr int SQ_F  = QT * LDS;      // 8704
static constexpr int SK_F  = KT * LDS;      // 4352
static constexpr int SVT_F = D_K * KT;      // 4096 (64 rows x 64 floats)
static constexpr int SP_F  = QT * LDS;      // 8704
static constexpr int SMEM_BYTES = (SQ_F + SK_F + SVT_F + SP_F) * 4;  // 103424

__global__ __launch_bounds__(256, 2) void attn_kernel(
    const float* __restrict__ Qp, const float* __restrict__ Kp,
    const float* __restrict__ Vp, float* __restrict__ Op)
{
    extern __shared__ __align__(16) float sm[];
    float* sQ  = sm;
    float* sK  = sQ + SQ_F;
    float* sVt = sK + SK_F;
    float* sP  = sVt + SVT_F;

    const uint32_t sQb = (uint32_t)__cvta_generic_to_shared(sQ);
    const uint32_t sKb = (uint32_t)__cvta_generic_to_shared(sK);
    const uint32_t sVb = (uint32_t)__cvta_generic_to_shared(sVt);
    const uint32_t sPb = (uint32_t)__cvta_generic_to_shared(sP);

    const int tid  = threadIdx.x;
    const int wid  = tid >> 5;
    const int lane = tid & 31;
    const int wr   = wid * 16;        // warp's first q-row in tile

    // ldmatrix per-lane address components
    const int tile = lane >> 3;
    const int rt   = lane & 7;
    // A-frag tiles (sQ/sP): t0 rows+0 colLo, t1 rows+8 colLo, t2 rows+0 colHi, t3 rows+8 colHi
    const int a_row = wr + (tile & 1) * 8 + rt;
    const int a_c4  = (tile >> 1) * 4;
    // B-frag tiles (sK): t0 rowsJ colLo, t1 rowsJ colHi, t2 rowsJ+8 colLo, t3 rowsJ+8 colHi
    const int b_row = (tile >> 1) * 8 + rt;
    const int b_c4  = (tile & 1) * 4;
    const uint32_t aQbase = sQb + (uint32_t)(a_row * LDS + a_c4) * 4u;
    const uint32_t aPbase = sPb + (uint32_t)(a_row * LDS + a_c4) * 4u;

    const int bh  = blockIdx.y;
    const int b   = bh >> 4;
    const int h   = bh & 15;
    const int kvh = h >> 2;
    const int q0  = blockIdx.x * QT;

    const float qscale = 0.125f * 1.4426950408889634f;  // 1/sqrt(64)*log2(e)

    // ---- load + scale Q tile (128 x 64, tf32) ----
    {
        const int r  = tid >> 4;
        const int c4 = (tid & 15) * 4;
        #pragma unroll
        for (int i = 0; i < 8; i++) {
            const float4 v = *(const float4*)
                &Qp[(size_t)(b * Ss + q0 + r + i * 16) * D_MODEL + h * D_K + c4];
            float* p = &sQ[(r + i * 16) * LDS + c4];
            p[0] = to_tf32(v.x * qscale); p[1] = to_tf32(v.y * qscale);
            p[2] = to_tf32(v.z * qscale); p[3] = to_tf32(v.w * qscale);
        }
    }

    float Oacc[8][4];
    #pragma unroll
    for (int j = 0; j < 8; j++)
        #pragma unroll
        for (int i = 0; i < 4; i++) Oacc[j][i] = 0.0f;
    float m0 = -1e30f, m1 = -1e30f, l0 = 0.0f, l1 = 0.0f;

    for (int kt = 0; kt < Ss / KT; ++kt) {
        __syncthreads();   // previous iteration's readers of sK/sVt done

        // ---- K tile: rows = key index n, cols = feature k (LDS=68) ----
        {
            const int r  = tid >> 4;
            const int c4 = (tid & 15) * 4;
            #pragma unroll
            for (int i = 0; i < 4; i++) {
                const size_t base =
                    (size_t)(b * Ss + kt * KT + r + i * 16) * KV_D + kvh * D_K + c4;
                const float4 kv = *(const float4*)&Kp[base];
                float* pk = &sK[(r + i * 16) * LDS + c4];
                pk[0] = to_tf32(kv.x); pk[1] = to_tf32(kv.y);
                pk[2] = to_tf32(kv.z); pk[3] = to_tf32(kv.w);
            }
        }
        // ---- V tile: TRANSPOSED store; thread owns a 4(kv) x 4(d) block ----
        {
            const int c4  = (tid & 15) * 4;       // d chunk
            const int kv0 = (tid >> 4) * 4;       // 4 consecutive kv rows
            float4 mv[4];
            #pragma unroll
            for (int kx = 0; kx < 4; kx++) {
                const size_t base =
                    (size_t)(b * Ss + kt * KT + kv0 + kx) * KV_D + kvh * D_K + c4;
                mv[kx] = *(const float4*)&Vp[base];
            }
            const int cb = kv0 >> 2;
            #pragma unroll
            for (int i = 0; i < 4; i++) {
                const int d = c4 + i;
                float4 w;
                w.x = to_tf32(((const float*)&mv[0])[i]);
                w.y = to_tf32(((const float*)&mv[1])[i]);
                w.z = to_tf32(((const float*)&mv[2])[i]);
                w.w = to_tf32(((const float*)&mv[3])[i]);
                const int phys = cb ^ (d & 7);
                *(float4*)&sVt[d * KT + phys * 4] = w;
            }
        }
        __syncthreads();

        // ---- S = Q @ K^T (warp 16x64, registers) ----
        float Sacc[8][4];
        #pragma unroll
        for (int j = 0; j < 8; j++)
            #pragma unroll
            for (int i = 0; i < 4; i++) Sacc[j][i] = 0.0f;

        #pragma unroll
        for (int kk = 0; kk < 8; kk++) {
            uint32_t a[4];
            ldsm_x4(a, aQbase + (uint32_t)(kk * 8) * 4u);
            #pragma unroll
            for (int j2 = 0; j2 < 4; j2++) {
                uint32_t bq[4];
                ldsm_x4(bq, sKb + (uint32_t)((j2 * 16 + b_row) * LDS + kk * 8 + b_c4) * 4u);
                mma_tf32(Sacc[2 * j2    ], a[0], a[1], a[2], a[3], bq[0], bq[1]);
                mma_tf32(Sacc[2 * j2 + 1], a[0], a[1], a[2], a[3], bq[2], bq[3]);
            }
        }

        // ---- online softmax in registers ----
        const int g = lane >> 2;
        const int t = lane & 3;
        float mx0 = -1e30f, mx1 = -1e30f;
        #pragma unroll
        for (int j = 0; j < 8; j++) {
            mx0 = fmaxf(mx0, fmaxf(Sacc[j][0], Sacc[j][1]));
            mx1 = fmaxf(mx1, fmaxf(Sacc[j][2], Sacc[j][3]));
        }
        mx0 = fmaxf(mx0, __shfl_xor_sync(0xffffffffu, mx0, 1));
        mx0 = fmaxf(mx0, __shfl_xor_sync(0xffffffffu, mx0, 2));
        mx1 = fmaxf(mx1, __shfl_xor_sync(0xffffffffu, mx1, 1));
        mx1 = fmaxf(mx1, __shfl_xor_sync(0xffffffffu, mx1, 2));
        const float mn0 = fmaxf(m0, mx0);
        const float mn1 = fmaxf(m1, mx1);
        const float al0 = ex2f(m0 - mn0);
        const float al1 = ex2f(m1 - mn1);
        m0 = mn0; m1 = mn1;

        float s0 = 0.0f, s1 = 0.0f;
        float2* pr0 = (float2*)&sP[(wr + g    ) * LDS + t * 2];
        float2* pr1 = (float2*)&sP[(wr + g + 8) * LDS + t * 2];
        #pragma unroll
        for (int j = 0; j < 8; j++) {
            const float p00 = ex2f(Sacc[j][0] - mn0);
            const float p01 = ex2f(Sacc[j][1] - mn0);
            const float p10 = ex2f(Sacc[j][2] - mn1);
            const float p11 = ex2f(Sacc[j][3] - mn1);
            s0 += p00 + p01;
            s1 += p10 + p11;
            pr0[j * 4] = make_float2(to_tf32(p00), to_tf32(p01));
            pr1[j * 4] = make_float2(to_tf32(p10), to_tf32(p11));
        }
        s0 += __shfl_xor_sync(0xffffffffu, s0, 1);
        s0 += __shfl_xor_sync(0xffffffffu, s0, 2);
        s1 += __shfl_xor_sync(0xffffffffu, s1, 1);
        s1 += __shfl_xor_sync(0xffffffffu, s1, 2);
        l0 = l0 * al0 + s0;
        l1 = l1 * al1 + s1;

        #pragma unroll
        for (int j = 0; j < 8; j++) {
            Oacc[j][0] *= al0; Oacc[j][1] *= al0;
            Oacc[j][2] *= al1; Oacc[j][3] *= al1;
        }
        // sP rows are warp-private: no __syncthreads() needed before PV.

        // ---- O += P @ V  (A from sP, B from sVt via swizzled LDSM) ----
        #pragma unroll
        for (int kk = 0; kk < 8; kk++) {
            uint32_t a[4];
            ldsm_x4(a, aPbase + (uint32_t)(kk * 8) * 4u);
            const int physc = (2 * kk + ((tile & 1))) ^ rt;
            #pragma unroll
            for (int j2 = 0; j2 < 4; j2++) {
                uint32_t bv[4];
                ldsm_x4(bv, sVb + (uint32_t)((j2 * 16 + b_row) * KT + physc * 4) * 4u);
                mma_tf32(Oacc[2 * j2    ], a[0], a[1], a[2], a[3], bv[0], bv[1]);
                mma_tf32(Oacc[2 * j2 + 1], a[0], a[1], a[2], a[3], bv[2], bv[3]);
            }
        }
    }

    // ---- normalize + write out (layout (b, s, h, d) == (M, 1024)) ----
    const int g = lane >> 2;
    const int t = lane & 3;
    const float inv0 = 1.0f / l0;
    const float inv1 = 1.0f / l1;
    float* d0 = &Op[(size_t)(b * Ss + q0 + wr + g    ) * D_MODEL + h * D_K + t * 2];
    float* d1 = &Op[(size_t)(b * Ss + q0 + wr + g + 8) * D_MODEL + h * D_K + t * 2];
    #pragma unroll
    for (int j = 0; j < 8; j++) {
        *(float2*)&d0[j * 8] = make_float2(Oacc[j][0] * inv0, Oacc[j][1] * inv0);
        *(float2*)&d1[j * 8] = make_float2(Oacc[j][2] * inv1, Oacc[j][3] * inv1);
    }
}

// ---------------------------------------------------------------------------
// Launch
// ---------------------------------------------------------------------------
extern "C" void kernel_launch(void* const* d_in, const int* in_sizes, int n_in,
                              void* d_out, int out_size)
{
    const float* q  = (const float*)d_in[0];
    const float* k  = (const float*)d_in[1];
    const float* v  = (const float*)d_in[2];
    const float* Wq = (const float*)d_in[3];
    const float* Wk = (const float*)d_in[4];
    const float* Wv = (const float*)d_in[5];
    const float* Wo = (const float*)d_in[6];
    float* out = (float*)d_out;

    float *gq, *gk, *gv, *go;
    cudaGetSymbolAddress((void**)&gq, g_Q);
    cudaGetSymbolAddress((void**)&gk, g_K);
    cudaGetSymbolAddress((void**)&gv, g_V);
    cudaGetSymbolAddress((void**)&go, g_O);

    cudaFuncSetAttribute(attn_kernel,
                         cudaFuncAttributeMaxDynamicSharedMemorySize, SMEM_BYTES);

    gemm_tf32_kernel<<<dim3(D_MODEL / GBN, MTOT / GBM), 256>>>(
        q, Wq, gq, MTOT, D_MODEL, D_MODEL);
    gemm_tf32_kernel<<<dim3(KV_D / GBN, MTOT / GBM), 256>>>(
        k, Wk, gk, MTOT, KV_D, D_MODEL);
    gemm_tf32_kernel<<<dim3(KV_D / GBN, MTOT / GBM), 256>>>(
        v, Wv, gv, MTOT, KV_D, D_MODEL);

    attn_kernel<<<dim3(Ss / QT, Bb * N_HEAD), 256, SMEM_BYTES>>>(gq, gk, gv, go);

    gemm_tf32_kernel<<<dim3(D_MODEL / GBN, MTOT / GBM), 256>>>(
        go, Wo, out, MTOT, D_MODEL, D_MODEL);
}

// round 5
// speedup vs baseline: 1.7294x; 1.7294x over previous
#include <cuda_runtime.h>
#include <cstdint>
#include <cstddef>

// ---------------------------------------------------------------------------
// Problem constants
// ---------------------------------------------------------------------------
static constexpr int D_MODEL = 1024;
static constexpr int N_HEAD  = 16;
static constexpr int N_KVH   = 4;
static constexpr int D_K     = 64;
static constexpr int Bb      = 2;
static constexpr int Ss      = 2048;
static constexpr int MTOT    = Bb * Ss;          // 4096
static constexpr int KV_D    = N_KVH * D_K;      // 256

// ---------------------------------------------------------------------------
// Scratch (no cudaMalloc allowed)
// ---------------------------------------------------------------------------
__device__ float g_Q[(size_t)MTOT * D_MODEL];
__device__ float g_K[(size_t)MTOT * KV_D];
__device__ float g_V[(size_t)MTOT * KV_D];
__device__ float g_O[(size_t)MTOT * D_MODEL];
__device__ float g_Xq[(size_t)MTOT * D_MODEL];   // tf32-rounded inputs
__device__ float g_Xk[(size_t)MTOT * D_MODEL];
__device__ float g_Xv[(size_t)MTOT * D_MODEL];
__device__ float g_WqT[(size_t)D_MODEL * D_MODEL];   // [N][K] transposed+tf32
__device__ float g_WkT[(size_t)KV_D * D_MODEL];
__device__ float g_WvT[(size_t)KV_D * D_MODEL];
__device__ float g_WoT[(size_t)D_MODEL * D_MODEL];

__device__ __forceinline__ float ex2f(float x) {
    float y;
    asm("ex2.approx.ftz.f32 %0, %1;" : "=f"(y) : "f"(x));
    return y;
}
__device__ __forceinline__ float to_tf32(float x) {
    uint32_t y;
    asm("cvt.rna.tf32.f32 %0, %1;" : "=r"(y) : "f"(x));
    return __uint_as_float(y);
}

// mma.sync m16n8k8 tf32: D += A*B, A row-major 16x8, B col-major 8x8
__device__ __forceinline__ void mma_tf32(float c[4],
                                         uint32_t a0, uint32_t a1, uint32_t a2, uint32_t a3,
                                         uint32_t b0, uint32_t b1) {
    asm volatile(
        "mma.sync.aligned.m16n8k8.row.col.f32.tf32.tf32.f32 "
        "{%0,%1,%2,%3}, {%4,%5,%6,%7}, {%8,%9}, {%0,%1,%2,%3};\n"
        : "+f"(c[0]), "+f"(c[1]), "+f"(c[2]), "+f"(c[3])
        : "r"(a0), "r"(a1), "r"(a2), "r"(a3), "r"(b0), "r"(b1));
}

__device__ __forceinline__ void ldsm_x4(uint32_t r[4], uint32_t addr) {
    asm volatile(
        "ldmatrix.sync.aligned.m8n8.x4.shared.b16 {%0,%1,%2,%3}, [%4];\n"
        : "=r"(r[0]), "=r"(r[1]), "=r"(r[2]), "=r"(r[3]) : "r"(addr));
}

__device__ __forceinline__ void cp_async16(uint32_t dst, const void* src) {
    asm volatile("cp.async.ca.shared.global [%0], [%1], 16;\n" :: "r"(dst), "l"(src));
}
__device__ __forceinline__ void cp_commit() {
    asm volatile("cp.async.commit_group;\n");
}
template<int N>
__device__ __forceinline__ void cp_wait() {
    asm volatile("cp.async.wait_group %0;\n" :: "n"(N));
}

// ---------------------------------------------------------------------------
// Aux: tf32 round-copy (grid-stride, float4)
// ---------------------------------------------------------------------------
__global__ void cvt_copy_kernel(const float* __restrict__ src,
                                float* __restrict__ dst, int n4)
{
    int i = blockIdx.x * blockDim.x + threadIdx.x;
    const int stride = gridDim.x * blockDim.x;
    for (; i < n4; i += stride) {
        float4 v = ((const float4*)src)[i];
        v.x = to_tf32(v.x); v.y = to_tf32(v.y);
        v.z = to_tf32(v.z); v.w = to_tf32(v.w);
        ((float4*)dst)[i] = v;
    }
}

// ---------------------------------------------------------------------------
// Aux: weight transpose + tf32 round: out[n][k] = tf32(in[k][n]); dims % 32 == 0
// ---------------------------------------------------------------------------
__global__ void transpose_cvt_kernel(const float* __restrict__ in,
                                     float* __restrict__ out, int K, int N)
{
    __shared__ float tl[32][33];
    const int k0 = blockIdx.y * 32;
    const int n0 = blockIdx.x * 32;
    #pragma unroll
    for (int i = 0; i < 4; i++)
        tl[threadIdx.y + i * 8][threadIdx.x] =
            in[(size_t)(k0 + threadIdx.y + i * 8) * N + n0 + threadIdx.x];
    __syncthreads();
    #pragma unroll
    for (int i = 0; i < 4; i++)
        out[(size_t)(n0 + threadIdx.y + i * 8) * K + k0 + threadIdx.x] =
            to_tf32(tl[threadIdx.x][threadIdx.y + i * 8]);
}

// ---------------------------------------------------------------------------
// GEMM v3: C[M,N] = A[M,K] @ Bt[N,K]^T. Inputs already tf32-rounded.
// Block 128 x BN, K-chunk 32, 256 threads. cp.async double-buffered smem,
// ldmatrix + mma.m16n8k8. BN=128: 8 warps 2m x 4n, warp 64x32.
//                          BN=64 : 8 warps 4m x 2n, warp 32x32.
// ---------------------------------------------------------------------------
static constexpr int LDT = 36;   // 32 + 4 pad floats

template<int BN>
__global__ __launch_bounds__(256, 2) void gemm_v3_kernel(
    const float* __restrict__ A, const float* __restrict__ Bt,
    float* __restrict__ C, int M, int N, int K, int round_out)
{
    constexpr int NW_N = BN / 32;
    constexpr int NW_M = 8 / NW_N;
    constexpr int WM   = 128 / NW_M;      // 64 or 32
    constexpr int MFR  = WM / 16;         // 4 or 2
    constexpr int BF4  = BN / 32;         // B float4s per thread (4 or 2)

    extern __shared__ __align__(16) float smem_g[];
    float* sA[2] = { smem_g, smem_g + 128 * LDT };
    float* sB[2] = { smem_g + 2 * 128 * LDT, smem_g + 2 * 128 * LDT + BN * LDT };
    const uint32_t uA[2] = { (uint32_t)__cvta_generic_to_shared(sA[0]),
                             (uint32_t)__cvta_generic_to_shared(sA[1]) };
    const uint32_t uB[2] = { (uint32_t)__cvta_generic_to_shared(sB[0]),
                             (uint32_t)__cvta_generic_to_shared(sB[1]) };

    const int tid  = threadIdx.x;
    const int wid  = tid >> 5;
    const int lane = tid & 31;
    const int wm   = wid / NW_N;
    const int wn   = wid % NW_N;
    const int bm   = blockIdx.y * 128;
    const int bn   = blockIdx.x * BN;

    // ldmatrix lane addressing (proven in attn kernel)
    const int tile = lane >> 3;
    const int rt   = lane & 7;
    const int a_rl = (tile & 1) * 8 + rt;      // row within 16-row group
    const int a_c4 = (tile >> 1) * 4;
    const int b_rl = (tile >> 1) * 8 + rt;
    const int b_c4 = (tile & 1) * 4;

    float acc[MFR][4][4];
    #pragma unroll
    for (int i = 0; i < MFR; i++)
        #pragma unroll
        for (int j = 0; j < 4; j++)
            #pragma unroll
            for (int e = 0; e < 4; e++) acc[i][j][e] = 0.0f;

    const int NC = K >> 5;    // K / 32 chunks

    // ---- stage chunk 0 ----
    {
        #pragma unroll
        for (int i = 0; i < 4; i++) {
            const int idx = tid + i * 256;
            cp_async16(uA[0] + (uint32_t)((idx >> 3) * LDT + (idx & 7) * 4) * 4u,
                       &A[(size_t)(bm + (idx >> 3)) * K + (idx & 7) * 4]);
        }
        #pragma unroll
        for (int i = 0; i < BF4; i++) {
            const int idx = tid + i * 256;
            cp_async16(uB[0] + (uint32_t)((idx >> 3) * LDT + (idx & 7) * 4) * 4u,
                       &Bt[(size_t)(bn + (idx >> 3)) * K + (idx & 7) * 4]);
        }
        cp_commit();
    }

    for (int c = 0; c < NC; ++c) {
        const int cur = c & 1;
        if (c + 1 < NC) {
            const int nxt = cur ^ 1;
            const int k0  = (c + 1) * 32;
            #pragma unroll
            for (int i = 0; i < 4; i++) {
                const int idx = tid + i * 256;
                cp_async16(uA[nxt] + (uint32_t)((idx >> 3) * LDT + (idx & 7) * 4) * 4u,
                           &A[(size_t)(bm + (idx >> 3)) * K + k0 + (idx & 7) * 4]);
            }
            #pragma unroll
            for (int i = 0; i < BF4; i++) {
                const int idx = tid + i * 256;
                cp_async16(uB[nxt] + (uint32_t)((idx >> 3) * LDT + (idx & 7) * 4) * 4u,
                           &Bt[(size_t)(bn + (idx >> 3)) * K + k0 + (idx & 7) * 4]);
            }
            cp_commit();
            cp_wait<1>();
        } else {
            cp_wait<0>();
        }
        __syncthreads();

        const uint32_t ua = uA[cur];
        const uint32_t ub = uB[cur];
        #pragma unroll
        for (int kk = 0; kk < 4; kk++) {
            uint32_t afr[MFR][4];
            #pragma unroll
            for (int i = 0; i < MFR; i++)
                ldsm_x4(afr[i], ua + (uint32_t)((wm * WM + i * 16 + a_rl) * LDT
                                                + kk * 8 + a_c4) * 4u);
            #pragma unroll
            for (int j2 = 0; j2 < 2; j2++) {
                uint32_t bfr[4];
                ldsm_x4(bfr, ub + (uint32_t)((wn * 32 + j2 * 16 + b_rl) * LDT
                                             + kk * 8 + b_c4) * 4u);
                #pragma unroll
                for (int i = 0; i < MFR; i++) {
                    mma_tf32(acc[i][j2 * 2    ], afr[i][0], afr[i][1], afr[i][2], afr[i][3],
                             bfr[0], bfr[1]);
                    mma_tf32(acc[i][j2 * 2 + 1], afr[i][0], afr[i][1], afr[i][2], afr[i][3],
                             bfr[2], bfr[3]);
                }
            }
        }
        __syncthreads();
    }

    // ---- epilogue ----
    const int g = lane >> 2;
    const int t = lane & 3;
    #pragma unroll
    for (int i = 0; i < MFR; i++) {
        #pragma unroll
        for (int j = 0; j < 4; j++) {
            const int r0 = bm + wm * WM + i * 16 + g;
            const int cc = bn + wn * 32 + j * 8 + t * 2;
            float2 v0 = make_float2(acc[i][j][0], acc[i][j][1]);
            float2 v1 = make_float2(acc[i][j][2], acc[i][j][3]);
            if (round_out) {
                v0.x = to_tf32(v0.x); v0.y = to_tf32(v0.y);
                v1.x = to_tf32(v1.x); v1.y = to_tf32(v1.y);
            }
            *(float2*)&C[(size_t)r0 * N + cc]       = v0;
            *(float2*)&C[(size_t)(r0 + 8) * N + cc] = v1;
        }
    }
}

// ---------------------------------------------------------------------------
// Flash attention (GQA). Q fragments loop-invariant in registers.
// CTA = 128 q-rows x (b,h); 8 warps, warp 16 rows. KV tile 64. Inputs tf32.
// sQ (staging, reused as sP after Q-frag load), sK row-major, sVt transposed.
// ---------------------------------------------------------------------------
static constexpr int QT  = 128;
static constexpr int KT  = 64;
static constexpr int LDS = 68;

static constexpr int SQ_F  = QT * LDS;      // 8704 (aliased by sP)
static constexpr int SK_F  = KT * LDS;      // 4352
static constexpr int SVT_F = D_K * KT;      // 4096
static constexpr int ATTN_SMEM_BYTES = (SQ_F + SK_F + SVT_F) * 4;  // 68608

__global__ __launch_bounds__(256, 2) void attn_kernel(
    const float* __restrict__ Qp, const float* __restrict__ Kp,
    const float* __restrict__ Vp, float* __restrict__ Op)
{
    extern __shared__ __align__(16) float sm[];
    float* sQ  = sm;           // staging for Q; reused as sP after frag load
    float* sK  = sQ + SQ_F;
    float* sVt = sK + SK_F;
    float* sP  = sQ;

    const uint32_t sQb = (uint32_t)__cvta_generic_to_shared(sQ);
    const uint32_t sKb = (uint32_t)__cvta_generic_to_shared(sK);
    const uint32_t sVb = (uint32_t)__cvta_generic_to_shared(sVt);

    const int tid  = threadIdx.x;
    const int wid  = tid >> 5;
    const int lane = tid & 31;
    const int wr   = wid * 16;

    const int tile = lane >> 3;
    const int rt   = lane & 7;
    const int a_row = wr + (tile & 1) * 8 + rt;
    const int a_c4  = (tile >> 1) * 4;
    const int b_row = (tile >> 1) * 8 + rt;
    const int b_c4  = (tile & 1) * 4;
    const uint32_t aQbase = sQb + (uint32_t)(a_row * LDS + a_c4) * 4u;

    const int bh  = blockIdx.y;
    const int b   = bh >> 4;
    const int h   = bh & 15;
    const int kvh = h >> 2;
    const int q0  = blockIdx.x * QT;

    const float qscale = 0.125f * 1.4426950408889634f;  // 1/sqrt(64)*log2(e)

    // ---- stage + scale Q tile, then load fragments into registers ----
    {
        const int r  = tid >> 4;
        const int c4 = (tid & 15) * 4;
        #pragma unroll
        for (int i = 0; i < 8; i++) {
            const float4 v = *(const float4*)
                &Qp[(size_t)(b * Ss + q0 + r + i * 16) * D_MODEL + h * D_K + c4];
            float* p = &sQ[(r + i * 16) * LDS + c4];
            p[0] = to_tf32(v.x * qscale); p[1] = to_tf32(v.y * qscale);
            p[2] = to_tf32(v.z * qscale); p[3] = to_tf32(v.w * qscale);
        }
    }
    __syncthreads();
    uint32_t Qfrag[8][4];
    #pragma unroll
    for (int kk = 0; kk < 8; kk++)
        ldsm_x4(Qfrag[kk], aQbase + (uint32_t)(kk * 8) * 4u);

    float Oacc[8][4];
    #pragma unroll
    for (int j = 0; j < 8; j++)
        #pragma unroll
        for (int i = 0; i < 4; i++) Oacc[j][i] = 0.0f;
    float m0 = -1e30f, m1 = -1e30f, l0 = 0.0f, l1 = 0.0f;

    for (int kt = 0; kt < Ss / KT; ++kt) {
        __syncthreads();   // prior readers of sK/sVt (and Qfrag loads) done

        // ---- K tile (plain copy; values already tf32) ----
        {
            const int r  = tid >> 4;
            const int c4 = (tid & 15) * 4;
            #pragma unroll
            for (int i = 0; i < 4; i++) {
                const size_t base =
                    (size_t)(b * Ss + kt * KT + r + i * 16) * KV_D + kvh * D_K + c4;
                *(float4*)&sK[(r + i * 16) * LDS + c4] = *(const float4*)&Kp[base];
            }
        }
        // ---- V tile transposed (4x4 register transpose, xor swizzle) ----
        {
            const int c4  = (tid & 15) * 4;
            const int kv0 = (tid >> 4) * 4;
            float4 mv[4];
            #pragma unroll
            for (int kx = 0; kx < 4; kx++) {
                const size_t base =
                    (size_t)(b * Ss + kt * KT + kv0 + kx) * KV_D + kvh * D_K + c4;
                mv[kx] = *(const float4*)&Vp[base];
            }
            const int cb = kv0 >> 2;
            #pragma unroll
            for (int i = 0; i < 4; i++) {
                const int d = c4 + i;
                float4 w;
                w.x = ((const float*)&mv[0])[i];
                w.y = ((const float*)&mv[1])[i];
                w.z = ((const float*)&mv[2])[i];
                w.w = ((const float*)&mv[3])[i];
                const int phys = cb ^ (d & 7);
                *(float4*)&sVt[d * KT + phys * 4] = w;
            }
        }
        __syncthreads();

        // ---- S = Q @ K^T (Q from registers) ----
        float Sacc[8][4];
        #pragma unroll
        for (int j = 0; j < 8; j++)
            #pragma unroll
            for (int i = 0; i < 4; i++) Sacc[j][i] = 0.0f;

        #pragma unroll
        for (int kk = 0; kk < 8; kk++) {
            #pragma unroll
            for (int j2 = 0; j2 < 4; j2++) {
                uint32_t bq[4];
                ldsm_x4(bq, sKb + (uint32_t)((j2 * 16 + b_row) * LDS + kk * 8 + b_c4) * 4u);
                mma_tf32(Sacc[2 * j2    ], Qfrag[kk][0], Qfrag[kk][1], Qfrag[kk][2], Qfrag[kk][3],
                         bq[0], bq[1]);
                mma_tf32(Sacc[2 * j2 + 1], Qfrag[kk][0], Qfrag[kk][1], Qfrag[kk][2], Qfrag[kk][3],
                         bq[2], bq[3]);
            }
        }

        // ---- online softmax in registers ----
        const int g = lane >> 2;
        const int t = lane & 3;
        float mx0 = -1e30f, mx1 = -1e30f;
        #pragma unroll
        for (int j = 0; j < 8; j++) {
            mx0 = fmaxf(mx0, fmaxf(Sacc[j][0], Sacc[j][1]));
            mx1 = fmaxf(mx1, fmaxf(Sacc[j][2], Sacc[j][3]));
        }
        mx0 = fmaxf(mx0, __shfl_xor_sync(0xffffffffu, mx0, 1));
        mx0 = fmaxf(mx0, __shfl_xor_sync(0xffffffffu, mx0, 2));
        mx1 = fmaxf(mx1, __shfl_xor_sync(0xffffffffu, mx1, 1));
        mx1 = fmaxf(mx1, __shfl_xor_sync(0xffffffffu, mx1, 2));
        const float mn0 = fmaxf(m0, mx0);
        const float mn1 = fmaxf(m1, mx1);
        const float al0 = ex2f(m0 - mn0);
        const float al1 = ex2f(m1 - mn1);
        m0 = mn0; m1 = mn1;

        float s0 = 0.0f, s1 = 0.0f;
        float2* pr0 = (float2*)&sP[(wr + g    ) * LDS + t * 2];
        float2* pr1 = (float2*)&sP[(wr + g + 8) * LDS + t * 2];
        #pragma unroll
        for (int j = 0; j < 8; j++) {
            const float p00 = ex2f(Sacc[j][0] - mn0);
            const float p01 = ex2f(Sacc[j][1] - mn0);
            const float p10 = ex2f(Sacc[j][2] - mn1);
            const float p11 = ex2f(Sacc[j][3] - mn1);
            s0 += p00 + p01;
            s1 += p10 + p11;
            pr0[j * 4] = make_float2(to_tf32(p00), to_tf32(p01));
            pr1[j * 4] = make_float2(to_tf32(p10), to_tf32(p11));
        }
        s0 += __shfl_xor_sync(0xffffffffu, s0, 1);
        s0 += __shfl_xor_sync(0xffffffffu, s0, 2);
        s1 += __shfl_xor_sync(0xffffffffu, s1, 1);
        s1 += __shfl_xor_sync(0xffffffffu, s1, 2);
        l0 = l0 * al0 + s0;
        l1 = l1 * al1 + s1;

        #pragma unroll
        for (int j = 0; j < 8; j++) {
            Oacc[j][0] *= al0; Oacc[j][1] *= al0;
            Oacc[j][2] *= al1; Oacc[j][3] *= al1;
        }
        // sP rows are warp-private: no block sync needed before PV.

        // ---- O += P @ V ----
        const uint32_t aPbase = sQb + (uint32_t)(a_row * LDS + a_c4) * 4u;
        #pragma unroll
        for (int kk = 0; kk < 8; kk++) {
            uint32_t a[4];
            ldsm_x4(a, aPbase + (uint32_t)(kk * 8) * 4u);
            const int physc = (2 * kk + (tile & 1)) ^ rt;
            #pragma unroll
            for (int j2 = 0; j2 < 4; j2++) {
                uint32_t bv[4];
                ldsm_x4(bv, sVb + (uint32_t)((j2 * 16 + b_row) * KT + physc * 4) * 4u);
                mma_tf32(Oacc[2 * j2    ], a[0], a[1], a[2], a[3], bv[0], bv[1]);
                mma_tf32(Oacc[2 * j2 + 1], a[0], a[1], a[2], a[3], bv[2], bv[3]);
            }
        }
    }

    // ---- normalize + write out, tf32-rounded (feeds W_o GEMM directly) ----
    const int g = lane >> 2;
    const int t = lane & 3;
    const float inv0 = 1.0f / l0;
    const float inv1 = 1.0f / l1;
    float* d0 = &Op[(size_t)(b * Ss + q0 + wr + g    ) * D_MODEL + h * D_K + t * 2];
    float* d1 = &Op[(size_t)(b * Ss + q0 + wr + g + 8) * D_MODEL + h * D_K + t * 2];
    #pragma unroll
    for (int j = 0; j < 8; j++) {
        *(float2*)&d0[j * 8] = make_float2(to_tf32(Oacc[j][0] * inv0),
                                           to_tf32(Oacc[j][1] * inv0));
        *(float2*)&d1[j * 8] = make_float2(to_tf32(Oacc[j][2] * inv1),
                                           to_tf32(Oacc[j][3] * inv1));
    }
}

// ---------------------------------------------------------------------------
// Launch
// ---------------------------------------------------------------------------
extern "C" void kernel_launch(void* const* d_in, const int* in_sizes, int n_in,
                              void* d_out, int out_size)
{
    const float* q  = (const float*)d_in[0];
    const float* k  = (const float*)d_in[1];
    const float* v  = (const float*)d_in[2];
    const float* Wq = (const float*)d_in[3];
    const float* Wk = (const float*)d_in[4];
    const float* Wv = (const float*)d_in[5];
    const float* Wo = (const float*)d_in[6];
    float* out = (float*)d_out;

    float *gq, *gk, *gv, *go, *xq, *xk, *xv, *wqt, *wkt, *wvt, *wot;
    cudaGetSymbolAddress((void**)&gq,  g_Q);
    cudaGetSymbolAddress((void**)&gk,  g_K);
    cudaGetSymbolAddress((void**)&gv,  g_V);
    cudaGetSymbolAddress((void**)&go,  g_O);
    cudaGetSymbolAddress((void**)&xq,  g_Xq);
    cudaGetSymbolAddress((void**)&xk,  g_Xk);
    cudaGetSymbolAddress((void**)&xv,  g_Xv);
    cudaGetSymbolAddress((void**)&wqt, g_WqT);
    cudaGetSymbolAddress((void**)&wkt, g_WkT);
    cudaGetSymbolAddress((void**)&wvt, g_WvT);
    cudaGetSymbolAddress((void**)&wot, g_WoT);

    const int smem128 = 2 * (128 + 128) * LDT * 4;   // 73728
    const int smem64  = 2 * (128 + 64) * LDT * 4;    // 55296
    cudaFuncSetAttribute(gemm_v3_kernel<128>,
                         cudaFuncAttributeMaxDynamicSharedMemorySize, smem128);
    cudaFuncSetAttribute(gemm_v3_kernel<64>,
                         cudaFuncAttributeMaxDynamicSharedMemorySize, smem64);
    cudaFuncSetAttribute(attn_kernel,
                         cudaFuncAttributeMaxDynamicSharedMemorySize, ATTN_SMEM_BYTES);

    // ---- pre-convert inputs to tf32 ----
    const int n4 = MTOT * D_MODEL / 4;
    cvt_copy_kernel<<<1024, 256>>>(q, xq, n4);
    cvt_copy_kernel<<<1024, 256>>>(k, xk, n4);
    cvt_copy_kernel<<<1024, 256>>>(v, xv, n4);

    // ---- transpose + round weights: Wt[n][k] ----
    transpose_cvt_kernel<<<dim3(D_MODEL / 32, D_MODEL / 32), dim3(32, 8)>>>(Wq, wqt, D_MODEL, D_MODEL);
    transpose_cvt_kernel<<<dim3(KV_D / 32,   D_MODEL / 32), dim3(32, 8)>>>(Wk, wkt, D_MODEL, KV_D);
    transpose_cvt_kernel<<<dim3(KV_D / 32,   D_MODEL / 32), dim3(32, 8)>>>(Wv, wvt, D_MODEL, KV_D);
    transpose_cvt_kernel<<<dim3(D_MODEL / 32, D_MODEL / 32), dim3(32, 8)>>>(Wo, wot, D_MODEL, D_MODEL);

    // ---- projections ----
    gemm_v3_kernel<128><<<dim3(D_MODEL / 128, MTOT / 128), 256, smem128>>>(
        xq, wqt, gq, MTOT, D_MODEL, D_MODEL, 1);
    gemm_v3_kernel<64><<<dim3(KV_D / 64, MTOT / 128), 256, smem64>>>(
        xk, wkt, gk, MTOT, KV_D, D_MODEL, 1);
    gemm_v3_kernel<64><<<dim3(KV_D / 64, MTOT / 128), 256, smem64>>>(
        xv, wvt, gv, MTOT, KV_D, D_MODEL, 1);

    // ---- attention ----
    attn_kernel<<<dim3(Ss / QT, Bb * N_HEAD), 256, ATTN_SMEM_BYTES>>>(gq, gk, gv, go);

    // ---- output projection (fp32 output, no rounding) ----
    gemm_v3_kernel<128><<<dim3(D_MODEL / 128, MTOT / 128), 256, smem128>>>(
        go, wot, out, MTOT, D_MODEL, D_MODEL, 0);
}

// round 6
// speedup vs baseline: 1.7881x; 1.0339x over previous
#include <cuda_runtime.h>
#include <cstdint>
#include <cstddef>

// ---------------------------------------------------------------------------
// Problem constants
// ---------------------------------------------------------------------------
static constexpr int D_MODEL = 1024;
static constexpr int N_HEAD  = 16;
static constexpr int N_KVH   = 4;
static constexpr int D_K     = 64;
static constexpr int Bb      = 2;
static constexpr int Ss      = 2048;
static constexpr int MTOT    = Bb * Ss;          // 4096
static constexpr int KV_D    = N_KVH * D_K;      // 256

// ---------------------------------------------------------------------------
// Scratch (no cudaMalloc allowed)
// ---------------------------------------------------------------------------
__device__ float g_Q[(size_t)MTOT * D_MODEL];
__device__ float g_K[(size_t)MTOT * KV_D];
__device__ float g_V[(size_t)MTOT * KV_D];
__device__ float g_O[(size_t)MTOT * D_MODEL];
__device__ float g_Xq[(size_t)MTOT * D_MODEL];   // tf32-rounded inputs
__device__ float g_Xk[(size_t)MTOT * D_MODEL];
__device__ float g_Xv[(size_t)MTOT * D_MODEL];
__device__ float g_WqT[(size_t)D_MODEL * D_MODEL];   // [N][K] transposed+tf32
__device__ float g_WkT[(size_t)KV_D * D_MODEL];
__device__ float g_WvT[(size_t)KV_D * D_MODEL];
__device__ float g_WoT[(size_t)D_MODEL * D_MODEL];

__device__ __forceinline__ float ex2f(float x) {
    float y;
    asm("ex2.approx.ftz.f32 %0, %1;" : "=f"(y) : "f"(x));
    return y;
}
__device__ __forceinline__ float to_tf32(float x) {
    uint32_t y;
    asm("cvt.rna.tf32.f32 %0, %1;" : "=r"(y) : "f"(x));
    return __uint_as_float(y);
}

// mma.sync m16n8k8 tf32: D += A*B, A row-major 16x8, B col-major 8x8
__device__ __forceinline__ void mma_tf32(float c[4],
                                         uint32_t a0, uint32_t a1, uint32_t a2, uint32_t a3,
                                         uint32_t b0, uint32_t b1) {
    asm volatile(
        "mma.sync.aligned.m16n8k8.row.col.f32.tf32.tf32.f32 "
        "{%0,%1,%2,%3}, {%4,%5,%6,%7}, {%8,%9}, {%0,%1,%2,%3};\n"
        : "+f"(c[0]), "+f"(c[1]), "+f"(c[2]), "+f"(c[3])
        : "r"(a0), "r"(a1), "r"(a2), "r"(a3), "r"(b0), "r"(b1));
}

__device__ __forceinline__ void ldsm_x4(uint32_t r[4], uint32_t addr) {
    asm volatile(
        "ldmatrix.sync.aligned.m8n8.x4.shared.b16 {%0,%1,%2,%3}, [%4];\n"
        : "=r"(r[0]), "=r"(r[1]), "=r"(r[2]), "=r"(r[3]) : "r"(addr));
}

__device__ __forceinline__ void cp_async16(uint32_t dst, const void* src) {
    asm volatile("cp.async.ca.shared.global [%0], [%1], 16;\n" :: "r"(dst), "l"(src));
}
__device__ __forceinline__ void cp_commit() {
    asm volatile("cp.async.commit_group;\n");
}
template<int N>
__device__ __forceinline__ void cp_wait() {
    asm volatile("cp.async.wait_group %0;\n" :: "n"(N));
}

// ---------------------------------------------------------------------------
// Aux: tf32 round-copy for q, k, v in one launch (z selects array)
// ---------------------------------------------------------------------------
__global__ void cvt3_kernel(const float* __restrict__ s0, float* __restrict__ d0,
                            const float* __restrict__ s1, float* __restrict__ d1,
                            const float* __restrict__ s2, float* __restrict__ d2,
                            int n4)
{
    const float* src = (blockIdx.z == 0) ? s0 : (blockIdx.z == 1) ? s1 : s2;
    float*       dst = (blockIdx.z == 0) ? d0 : (blockIdx.z == 1) ? d1 : d2;
    int i = blockIdx.x * blockDim.x + threadIdx.x;
    const int stride = gridDim.x * blockDim.x;
    for (; i < n4; i += stride) {
        float4 v = ((const float4*)src)[i];
        v.x = to_tf32(v.x); v.y = to_tf32(v.y);
        v.z = to_tf32(v.z); v.w = to_tf32(v.w);
        ((float4*)dst)[i] = v;
    }
}

// ---------------------------------------------------------------------------
// Aux: dual weight transpose + tf32 round (z selects pair member)
// out[n][k] = tf32(in[k][n]); dims % 32 == 0
// ---------------------------------------------------------------------------
__global__ void transpose2_kernel(const float* __restrict__ in0, float* __restrict__ out0,
                                  const float* __restrict__ in1, float* __restrict__ out1,
                                  int K, int N)
{
    const float* in  = blockIdx.z ? in1 : in0;
    float*       out = blockIdx.z ? out1 : out0;
    __shared__ float tl[32][33];
    const int k0 = blockIdx.y * 32;
    const int n0 = blockIdx.x * 32;
    #pragma unroll
    for (int i = 0; i < 4; i++)
        tl[threadIdx.y + i * 8][threadIdx.x] =
            in[(size_t)(k0 + threadIdx.y + i * 8) * N + n0 + threadIdx.x];
    __syncthreads();
    #pragma unroll
    for (int i = 0; i < 4; i++)
        out[(size_t)(n0 + threadIdx.y + i * 8) * K + k0 + threadIdx.x] =
            to_tf32(tl[threadIdx.x][threadIdx.y + i * 8]);
}

// ---------------------------------------------------------------------------
// GEMM body: C[M,N] = A[M,K] @ Bt[N,K]^T. Inputs already tf32-rounded.
// Block 128 x BN, K-chunk 32, 256 threads, cp.async double-buffered,
// ldmatrix + mma.m16n8k8.
// ---------------------------------------------------------------------------
static constexpr int LDT = 36;   // 32 + 4 pad floats

template<int BN>
__device__ __forceinline__ void gemm_body(
    const float* __restrict__ A, const float* __restrict__ Bt,
    float* __restrict__ C, int N, int K, int round_out, float* smem_g)
{
    constexpr int NW_N = BN / 32;
    constexpr int NW_M = 8 / NW_N;
    constexpr int WM   = 128 / NW_M;      // 64 or 32
    constexpr int MFR  = WM / 16;         // 4 or 2
    constexpr int BF4  = BN / 32;

    const uint32_t uA[2] = { (uint32_t)__cvta_generic_to_shared(smem_g),
                             (uint32_t)__cvta_generic_to_shared(smem_g + 128 * LDT) };
    const uint32_t uB[2] = { (uint32_t)__cvta_generic_to_shared(smem_g + 2 * 128 * LDT),
                             (uint32_t)__cvta_generic_to_shared(smem_g + 2 * 128 * LDT + BN * LDT) };

    const int tid  = threadIdx.x;
    const int wid  = tid >> 5;
    const int lane = tid & 31;
    const int wm   = wid / NW_N;
    const int wn   = wid % NW_N;
    const int bm   = blockIdx.y * 128;
    const int bn   = blockIdx.x * BN;

    const int tile = lane >> 3;
    const int rt   = lane & 7;
    const int a_rl = (tile & 1) * 8 + rt;
    const int a_c4 = (tile >> 1) * 4;
    const int b_rl = (tile >> 1) * 8 + rt;
    const int b_c4 = (tile & 1) * 4;

    float acc[MFR][4][4];
    #pragma unroll
    for (int i = 0; i < MFR; i++)
        #pragma unroll
        for (int j = 0; j < 4; j++)
            #pragma unroll
            for (int e = 0; e < 4; e++) acc[i][j][e] = 0.0f;

    const int NC = K >> 5;

    {
        #pragma unroll
        for (int i = 0; i < 4; i++) {
            const int idx = tid + i * 256;
            cp_async16(uA[0] + (uint32_t)((idx >> 3) * LDT + (idx & 7) * 4) * 4u,
                       &A[(size_t)(bm + (idx >> 3)) * K + (idx & 7) * 4]);
        }
        #pragma unroll
        for (int i = 0; i < BF4; i++) {
            const int idx = tid + i * 256;
            cp_async16(uB[0] + (uint32_t)((idx >> 3) * LDT + (idx & 7) * 4) * 4u,
                       &Bt[(size_t)(bn + (idx >> 3)) * K + (idx & 7) * 4]);
        }
        cp_commit();
    }

    for (int c = 0; c < NC; ++c) {
        const int cur = c & 1;
        if (c + 1 < NC) {
            const int nxt = cur ^ 1;
            const int k0  = (c + 1) * 32;
            #pragma unroll
            for (int i = 0; i < 4; i++) {
                const int idx = tid + i * 256;
                cp_async16(uA[nxt] + (uint32_t)((idx >> 3) * LDT + (idx & 7) * 4) * 4u,
                           &A[(size_t)(bm + (idx >> 3)) * K + k0 + (idx & 7) * 4]);
            }
            #pragma unroll
            for (int i = 0; i < BF4; i++) {
                const int idx = tid + i * 256;
                cp_async16(uB[nxt] + (uint32_t)((idx >> 3) * LDT + (idx & 7) * 4) * 4u,
                           &Bt[(size_t)(bn + (idx >> 3)) * K + k0 + (idx & 7) * 4]);
            }
            cp_commit();
            cp_wait<1>();
        } else {
            cp_wait<0>();
        }
        __syncthreads();

        const uint32_t ua = uA[cur];
        const uint32_t ub = uB[cur];
        #pragma unroll
        for (int kk = 0; kk < 4; kk++) {
            uint32_t afr[MFR][4];
            #pragma unroll
            for (int i = 0; i < MFR; i++)
                ldsm_x4(afr[i], ua + (uint32_t)((wm * WM + i * 16 + a_rl) * LDT
                                                + kk * 8 + a_c4) * 4u);
            #pragma unroll
            for (int j2 = 0; j2 < 2; j2++) {
                uint32_t bfr[4];
                ldsm_x4(bfr, ub + (uint32_t)((wn * 32 + j2 * 16 + b_rl) * LDT
                                             + kk * 8 + b_c4) * 4u);
                #pragma unroll
                for (int i = 0; i < MFR; i++) {
                    mma_tf32(acc[i][j2 * 2    ], afr[i][0], afr[i][1], afr[i][2], afr[i][3],
                             bfr[0], bfr[1]);
                    mma_tf32(acc[i][j2 * 2 + 1], afr[i][0], afr[i][1], afr[i][2], afr[i][3],
                             bfr[2], bfr[3]);
                }
            }
        }
        __syncthreads();
    }

    const int g = lane >> 2;
    const int t = lane & 3;
    #pragma unroll
    for (int i = 0; i < MFR; i++) {
        #pragma unroll
        for (int j = 0; j < 4; j++) {
            const int r0 = bm + wm * WM + i * 16 + g;
            const int cc = bn + wn * 32 + j * 8 + t * 2;
            float2 v0 = make_float2(acc[i][j][0], acc[i][j][1]);
            float2 v1 = make_float2(acc[i][j][2], acc[i][j][3]);
            if (round_out) {
                v0.x = to_tf32(v0.x); v0.y = to_tf32(v0.y);
                v1.x = to_tf32(v1.x); v1.y = to_tf32(v1.y);
            }
            *(float2*)&C[(size_t)r0 * N + cc]       = v0;
            *(float2*)&C[(size_t)(r0 + 8) * N + cc] = v1;
        }
    }
}

template<int BN>
__global__ __launch_bounds__(256, 2) void gemm_single_kernel(
    const float* __restrict__ A, const float* __restrict__ Bt,
    float* __restrict__ C, int N, int K, int round_out)
{
    extern __shared__ __align__(16) float smem_g[];
    gemm_body<BN>(A, Bt, C, N, K, round_out, smem_g);
}

// K and V projections fused (blockIdx.z selects)
template<int BN>
__global__ __launch_bounds__(256, 2) void gemm_dual_kernel(
    const float* __restrict__ A0, const float* __restrict__ Bt0, float* __restrict__ C0,
    const float* __restrict__ A1, const float* __restrict__ Bt1, float* __restrict__ C1,
    int N, int K, int round_out)
{
    extern __shared__ __align__(16) float smem_g[];
    if (blockIdx.z == 0) gemm_body<BN>(A0, Bt0, C0, N, K, round_out, smem_g);
    else                 gemm_body<BN>(A1, Bt1, C1, N, K, round_out, smem_g);
}

// ---------------------------------------------------------------------------
// Flash attention (GQA). Q fragments in registers; K/V double-buffered in
// smem so only ONE __syncthreads per KV tile (stores to buf[kt&1] are fenced
// from iter kt-2's readers by iter kt-1's barrier).
// ---------------------------------------------------------------------------
static constexpr int QT  = 128;
static constexpr int KT  = 64;
static constexpr int LDS = 68;

static constexpr int SQ_F   = QT * LDS;          // 8704 (aliased by sP)
static constexpr int SK_F   = KT * LDS;          // 4352
static constexpr int SVT_F  = D_K * KT;          // 4096
static constexpr int BUF_F  = SK_F + SVT_F;      // 8448
static constexpr int ATTN_SMEM_BYTES = (SQ_F + 2 * BUF_F) * 4;  // 102400

__global__ __launch_bounds__(256, 2) void attn_kernel(
    const float* __restrict__ Qp, const float* __restrict__ Kp,
    const float* __restrict__ Vp, float* __restrict__ Op)
{
    extern __shared__ __align__(16) float sm[];
    float* sQ = sm;                       // staging for Q; reused as sP
    float* sP = sQ;

    const uint32_t sQb   = (uint32_t)__cvta_generic_to_shared(sQ);
    const uint32_t sBufb = sQb + (uint32_t)SQ_F * 4u;   // K/V buffers base

    const int tid  = threadIdx.x;
    const int wid  = tid >> 5;
    const int lane = tid & 31;
    const int wr   = wid * 16;

    const int tile = lane >> 3;
    const int rt   = lane & 7;
    const int a_row = wr + (tile & 1) * 8 + rt;
    const int a_c4  = (tile >> 1) * 4;
    const int b_row = (tile >> 1) * 8 + rt;
    const int b_c4  = (tile & 1) * 4;
    const uint32_t aQbase = sQb + (uint32_t)(a_row * LDS + a_c4) * 4u;

    const int bh  = blockIdx.y;
    const int b   = bh >> 4;
    const int h   = bh & 15;
    const int kvh = h >> 2;
    const int q0  = blockIdx.x * QT;

    const float qscale = 0.125f * 1.4426950408889634f;  // 1/sqrt(64)*log2(e)

    // ---- stage + scale Q tile, then load fragments into registers ----
    {
        const int r  = tid >> 4;
        const int c4 = (tid & 15) * 4;
        #pragma unroll
        for (int i = 0; i < 8; i++) {
            const float4 v = *(const float4*)
                &Qp[(size_t)(b * Ss + q0 + r + i * 16) * D_MODEL + h * D_K + c4];
            float* p = &sQ[(r + i * 16) * LDS + c4];
            p[0] = to_tf32(v.x * qscale); p[1] = to_tf32(v.y * qscale);
            p[2] = to_tf32(v.z * qscale); p[3] = to_tf32(v.w * qscale);
        }
    }
    __syncthreads();
    uint32_t Qfrag[8][4];
    #pragma unroll
    for (int kk = 0; kk < 8; kk++)
        ldsm_x4(Qfrag[kk], aQbase + (uint32_t)(kk * 8) * 4u);

    float Oacc[8][4];
    #pragma unroll
    for (int j = 0; j < 8; j++)
        #pragma unroll
        for (int i = 0; i < 4; i++) Oacc[j][i] = 0.0f;
    float m0 = -1e30f, m1 = -1e30f, l0 = 0.0f, l1 = 0.0f;

    for (int kt = 0; kt < Ss / KT; ++kt) {
        const int bufsel = kt & 1;
        float* sK  = sm + SQ_F + bufsel * BUF_F;
        float* sVt = sK + SK_F;
        const uint32_t sKb = sBufb + (uint32_t)(bufsel * BUF_F) * 4u;
        const uint32_t sVb = sKb + (uint32_t)SK_F * 4u;

        // ---- K tile (plain copy; values already tf32) ----
        {
            const int r  = tid >> 4;
            const int c4 = (tid & 15) * 4;
            #pragma unroll
            for (int i = 0; i < 4; i++) {
                const size_t base =
                    (size_t)(b * Ss + kt * KT + r + i * 16) * KV_D + kvh * D_K + c4;
                *(float4*)&sK[(r + i * 16) * LDS + c4] = *(const float4*)&Kp[base];
            }
        }
        // ---- V tile transposed (4x4 register transpose, xor swizzle) ----
        {
            const int c4  = (tid & 15) * 4;
            const int kv0 = (tid >> 4) * 4;
            float4 mv[4];
            #pragma unroll
            for (int kx = 0; kx < 4; kx++) {
                const size_t base =
                    (size_t)(b * Ss + kt * KT + kv0 + kx) * KV_D + kvh * D_K + c4;
                mv[kx] = *(const float4*)&Vp[base];
            }
            const int cb = kv0 >> 2;
            #pragma unroll
            for (int i = 0; i < 4; i++) {
                const int d = c4 + i;
                float4 w;
                w.x = ((const float*)&mv[0])[i];
                w.y = ((const float*)&mv[1])[i];
                w.z = ((const float*)&mv[2])[i];
                w.w = ((const float*)&mv[3])[i];
                const int phys = cb ^ (d & 7);
                *(float4*)&sVt[d * KT + phys * 4] = w;
            }
        }
        __syncthreads();   // the ONLY barrier per tile

        // ---- S = Q @ K^T (Q from registers) ----
        float Sacc[8][4];
        #pragma unroll
        for (int j = 0; j < 8; j++)
            #pragma unroll
            for (int i = 0; i < 4; i++) Sacc[j][i] = 0.0f;

        #pragma unroll
        for (int kk = 0; kk < 8; kk++) {
            #pragma unroll
            for (int j2 = 0; j2 < 4; j2++) {
                uint32_t bq[4];
                ldsm_x4(bq, sKb + (uint32_t)((j2 * 16 + b_row) * LDS + kk * 8 + b_c4) * 4u);
                mma_tf32(Sacc[2 * j2    ], Qfrag[kk][0], Qfrag[kk][1], Qfrag[kk][2], Qfrag[kk][3],
                         bq[0], bq[1]);
                mma_tf32(Sacc[2 * j2 + 1], Qfrag[kk][0], Qfrag[kk][1], Qfrag[kk][2], Qfrag[kk][3],
                         bq[2], bq[3]);
            }
        }

        // ---- online softmax in registers ----
        const int g = lane >> 2;
        const int t = lane & 3;
        float mx0 = -1e30f, mx1 = -1e30f;
        #pragma unroll
        for (int j = 0; j < 8; j++) {
            mx0 = fmaxf(mx0, fmaxf(Sacc[j][0], Sacc[j][1]));
            mx1 = fmaxf(mx1, fmaxf(Sacc[j][2], Sacc[j][3]));
        }
        mx0 = fmaxf(mx0, __shfl_xor_sync(0xffffffffu, mx0, 1));
        mx0 = fmaxf(mx0, __shfl_xor_sync(0xffffffffu, mx0, 2));
        mx1 = fmaxf(mx1, __shfl_xor_sync(0xffffffffu, mx1, 1));
        mx1 = fmaxf(mx1, __shfl_xor_sync(0xffffffffu, mx1, 2));
        const float mn0 = fmaxf(m0, mx0);
        const float mn1 = fmaxf(m1, mx1);
        const float al0 = ex2f(m0 - mn0);
        const float al1 = ex2f(m1 - mn1);
        m0 = mn0; m1 = mn1;

        float s0 = 0.0f, s1 = 0.0f;
        float2* pr0 = (float2*)&sP[(wr + g    ) * LDS + t * 2];
        float2* pr1 = (float2*)&sP[(wr + g + 8) * LDS + t * 2];
        #pragma unroll
        for (int j = 0; j < 8; j++) {
            const float p00 = ex2f(Sacc[j][0] - mn0);
            const float p01 = ex2f(Sacc[j][1] - mn0);
            const float p10 = ex2f(Sacc[j][2] - mn1);
            const float p11 = ex2f(Sacc[j][3] - mn1);
            s0 += p00 + p01;
            s1 += p10 + p11;
            pr0[j * 4] = make_float2(to_tf32(p00), to_tf32(p01));
            pr1[j * 4] = make_float2(to_tf32(p10), to_tf32(p11));
        }
        s0 += __shfl_xor_sync(0xffffffffu, s0, 1);
        s0 += __shfl_xor_sync(0xffffffffu, s0, 2);
        s1 += __shfl_xor_sync(0xffffffffu, s1, 1);
        s1 += __shfl_xor_sync(0xffffffffu, s1, 2);
        l0 = l0 * al0 + s0;
        l1 = l1 * al1 + s1;

        #pragma unroll
        for (int j = 0; j < 8; j++) {
            Oacc[j][0] *= al0; Oacc[j][1] *= al0;
            Oacc[j][2] *= al1; Oacc[j][3] *= al1;
        }
        // sP rows are warp-private: no block sync needed before PV.

        // ---- O += P @ V ----
        const uint32_t aPbase = sQb + (uint32_t)(a_row * LDS + a_c4) * 4u;
        #pragma unroll
        for (int kk = 0; kk < 8; kk++) {
            uint32_t a[4];
            ldsm_x4(a, aPbase + (uint32_t)(kk * 8) * 4u);
            const int physc = (2 * kk + (tile & 1)) ^ rt;
            #pragma unroll
            for (int j2 = 0; j2 < 4; j2++) {
                uint32_t bv[4];
                ldsm_x4(bv, sVb + (uint32_t)((j2 * 16 + b_row) * KT + physc * 4) * 4u);
                mma_tf32(Oacc[2 * j2    ], a[0], a[1], a[2], a[3], bv[0], bv[1]);
                mma_tf32(Oacc[2 * j2 + 1], a[0], a[1], a[2], a[3], bv[2], bv[3]);
            }
        }
    }

    // ---- normalize + write out, tf32-rounded (feeds W_o GEMM) ----
    const int g = lane >> 2;
    const int t = lane & 3;
    const float inv0 = 1.0f / l0;
    const float inv1 = 1.0f / l1;
    float* d0 = &Op[(size_t)(b * Ss + q0 + wr + g    ) * D_MODEL + h * D_K + t * 2];
    float* d1 = &Op[(size_t)(b * Ss + q0 + wr + g + 8) * D_MODEL + h * D_K + t * 2];
    #pragma unroll
    for (int j = 0; j < 8; j++) {
        *(float2*)&d0[j * 8] = make_float2(to_tf32(Oacc[j][0] * inv0),
                                           to_tf32(Oacc[j][1] * inv0));
        *(float2*)&d1[j * 8] = make_float2(to_tf32(Oacc[j][2] * inv1),
                                           to_tf32(Oacc[j][3] * inv1));
    }
}

// ---------------------------------------------------------------------------
// Launch
// ---------------------------------------------------------------------------
extern "C" void kernel_launch(void* const* d_in, const int* in_sizes, int n_in,
                              void* d_out, int out_size)
{
    const float* q  = (const float*)d_in[0];
    const float* k  = (const float*)d_in[1];
    const float* v  = (const float*)d_in[2];
    const float* Wq = (const float*)d_in[3];
    const float* Wk = (const float*)d_in[4];
    const float* Wv = (const float*)d_in[5];
    const float* Wo = (const float*)d_in[6];
    float* out = (float*)d_out;

    float *gq, *gk, *gv, *go, *xq, *xk, *xv, *wqt, *wkt, *wvt, *wot;
    cudaGetSymbolAddress((void**)&gq,  g_Q);
    cudaGetSymbolAddress((void**)&gk,  g_K);
    cudaGetSymbolAddress((void**)&gv,  g_V);
    cudaGetSymbolAddress((void**)&go,  g_O);
    cudaGetSymbolAddress((void**)&xq,  g_Xq);
    cudaGetSymbolAddress((void**)&xk,  g_Xk);
    cudaGetSymbolAddress((void**)&xv,  g_Xv);
    cudaGetSymbolAddress((void**)&wqt, g_WqT);
    cudaGetSymbolAddress((void**)&wkt, g_WkT);
    cudaGetSymbolAddress((void**)&wvt, g_WvT);
    cudaGetSymbolAddress((void**)&wot, g_WoT);

    const int smem128 = 2 * (128 + 128) * LDT * 4;   // 73728
    const int smem64  = 2 * (128 + 64) * LDT * 4;    // 55296
    cudaFuncSetAttribute(gemm_single_kernel<128>,
                         cudaFuncAttributeMaxDynamicSharedMemorySize, smem128);
    cudaFuncSetAttribute(gemm_dual_kernel<64>,
                         cudaFuncAttributeMaxDynamicSharedMemorySize, smem64);
    cudaFuncSetAttribute(attn_kernel,
                         cudaFuncAttributeMaxDynamicSharedMemorySize, ATTN_SMEM_BYTES);

    // ---- pre-convert inputs to tf32 (single launch) ----
    const int n4 = MTOT * D_MODEL / 4;
    cvt3_kernel<<<dim3(512, 1, 3), 256>>>(q, xq, k, xk, v, xv, n4);

    // ---- transpose + round weights (two launches) ----
    transpose2_kernel<<<dim3(D_MODEL / 32, D_MODEL / 32, 2), dim3(32, 8)>>>(
        Wq, wqt, Wo, wot, D_MODEL, D_MODEL);
    transpose2_kernel<<<dim3(KV_D / 32, D_MODEL / 32, 2), dim3(32, 8)>>>(
        Wk, wkt, Wv, wvt, D_MODEL, KV_D);

    // ---- Q projection ----
    gemm_single_kernel<128><<<dim3(D_MODEL / 128, MTOT / 128), 256, smem128>>>(
        xq, wqt, gq, D_MODEL, D_MODEL, 1);
    // ---- K + V projections fused ----
    gemm_dual_kernel<64><<<dim3(KV_D / 64, MTOT / 128, 2), 256, smem64>>>(
        xk, wkt, gk, xv, wvt, gv, KV_D, D_MODEL, 1);

    // ---- attention ----
    attn_kernel<<<dim3(Ss / QT, Bb * N_HEAD), 256, ATTN_SMEM_BYTES>>>(gq, gk, gv, go);

    // ---- output projection (fp32 output) ----
    gemm_single_kernel<128><<<dim3(D_MODEL / 128, MTOT / 128), 256, smem128>>>(
        go, wot, out, D_MODEL, D_MODEL, 0);
}